// round 8
// baseline (speedup 1.0000x reference)
#include <cuda_runtime.h>
#include <math.h>

#define NN 2048
#define MM 2048
#define KC 8
#define DD 64

#define FAB_OFF 0
#define GAB_OFF NN
#define FAA_OFF (NN + MM)
#define GBB_OFF (2 * NN + MM)
#define POT_SZ  (2 * (NN + MM))
#define NROWS   (2 * (NN + MM))

#define LOG2E_F 1.4426950408889634f
#define LN2_F   0.6931471805599453f
#define SENT    -3.4e38f

#define CGA_SZ 8
#define ROUND_GRID (CGA_SZ * KC)          // 64 CTAs, one 8-CTA cluster per kmeans cluster
#define COST_GRID 4416

// -------------------- static device scratch ---------------------------------
__device__ int   g_predx[NN];
__device__ int   g_ix[NN], g_iy[MM];
__device__ int   g_clx[NN], g_cly[MM];
__device__ int   g_cntx[KC], g_cnty[KC];
__device__ int   g_offx[KC + 1], g_offy[KC + 1];
__device__ int   g_offXY[KC + 1], g_offYX[KC + 1], g_offXX[KC + 1], g_offYY[KC + 1];
__device__ float g_l2cx[KC], g_l2cy[KC];
__device__ int   g_valid[KC];
__device__ float g_lossfil;
__device__ int   g_tOff[4 * KC + 1];
__device__ int   g_rowBase[KC + 1];       // cluster-contiguous row ranges
__device__ float g_hx[NN], g_hy[MM];
// row descriptors (cluster-contiguous order; computed once, read every round)
__device__ const float* g_rowC[NROWS];
__device__ int   g_rowPotIn[NROWS];
__device__ int   g_rowOut[NROWS];
__device__ int   g_rowN[NROWS];
__device__ float g_rowB2[NROWS];
// cost matrices
__device__ float g_Cxy[(size_t)NN * MM];
__device__ float g_Cyx[(size_t)NN * MM];
__device__ float g_Cxx[(size_t)NN * NN];
__device__ float g_Cyy[(size_t)MM * MM];
__device__ float g_pot[2][POT_SZ];

__device__ __forceinline__ float ex2_fast(float x) {
    float r;
    asm("ex2.approx.ftz.f32 %0, %1;" : "=f"(r) : "f"(x));
    return r;
}

// -------------------- 1) fused assign + norms -------------------------------
__global__ void k_prep(const float* __restrict__ x, const float* __restrict__ cc,
                       const float* __restrict__ y) {
    __shared__ float scc[KC * DD];
    for (int idx = threadIdx.x; idx < KC * DD; idx += blockDim.x) scc[idx] = cc[idx];
    __syncthreads();
    int t = blockIdx.x * blockDim.x + threadIdx.x;
    if (t < NN) {
        float xr[DD];
        float nrm = 0.f;
        const float4* xv = reinterpret_cast<const float4*>(x + (size_t)t * DD);
#pragma unroll
        for (int q = 0; q < DD / 4; q++) {
            float4 v = xv[q];
            xr[q*4+0]=v.x; xr[q*4+1]=v.y; xr[q*4+2]=v.z; xr[q*4+3]=v.w;
            nrm += v.x*v.x + v.y*v.y + v.z*v.z + v.w*v.w;
        }
        g_hx[t] = 0.5f * nrm;
        float best = 3.4e38f; int bk = 0;
#pragma unroll
        for (int k = 0; k < KC; k++) {
            float s = 0.f;
#pragma unroll 16
            for (int d = 0; d < DD; d++) {
                float u = xr[d] - scc[k * DD + d];
                s = fmaf(u, u, s);
            }
            if (s < best) { best = s; bk = k; }
        }
        g_predx[t] = bk;
    } else if (t < NN + MM) {
        int j = t - NN;
        const float4* v = reinterpret_cast<const float4*>(y + (size_t)j * DD);
        float s = 0.f;
#pragma unroll
        for (int q = 0; q < DD / 4; q++) { float4 a = v[q]; s += a.x*a.x + a.y*a.y + a.z*a.z + a.w*a.w; }
        g_hy[j] = 0.5f * s;
    }
}

// -------------------- 2) lists + offsets + row descriptors ------------------
__global__ void k_lists(const int* __restrict__ predy32, const float* __restrict__ fill) {
    __shared__ int sBase[2][KC];
    __shared__ int sCnt[2][KC];
    __shared__ int sOr;
    int w = threadIdx.x >> 5, lane = threadIdx.x & 31;

    if (threadIdx.x == 0) sOr = 0;
    __syncthreads();
    int orv = 0;
    for (int i = threadIdx.x; i < MM / 2; i += blockDim.x) orv |= predy32[2 * i + 1];
    atomicOr(&sOr, orv);
    __syncthreads();
    const int stride = (sOr == 0) ? 2 : 1;   // int64 (odd words 0) vs int32

    if (w < 2) {
        int nElem = (w == 0) ? NN : MM;
        int cnt[KC];
#pragma unroll
        for (int k = 0; k < KC; k++) cnt[k] = 0;
        for (int ch = 0; ch < nElem / 32; ch++) {
            int i = ch * 32 + lane;
            int v = (w == 0) ? g_predx[i] : (predy32[i * stride] & 7);
#pragma unroll
            for (int k = 0; k < KC; k++) cnt[k] += (v == k);
        }
#pragma unroll
        for (int k = 0; k < KC; k++) {
            int s = cnt[k];
            for (int o = 16; o; o >>= 1) s += __shfl_down_sync(0xffffffffu, s, o);
            if (lane == 0) sCnt[w][k] = s;
        }
        __syncwarp();
        if (lane == 0) {
            int off = 0;
            for (int k = 0; k < KC; k++) {
                int c = sCnt[w][k];
                sBase[w][k] = off;
                if (w == 0) { g_cntx[k] = c; g_offx[k] = off; }
                else        { g_cnty[k] = c; g_offy[k] = off; }
                off += c;
            }
            if (w == 0) g_offx[KC] = off; else g_offy[KC] = off;
        }
        __syncwarp();
        for (int ch = 0; ch < nElem / 32; ch++) {
            int i = ch * 32 + lane;
            int v = (w == 0) ? g_predx[i] : (predy32[i * stride] & 7);
            unsigned mask = __match_any_sync(0xffffffffu, v);
            unsigned lt = (1u << lane) - 1u;
            int rank = __popc(mask & lt);
            int myBase = sBase[w][v];
            __syncwarp();
            int pos = myBase + rank;
            if (w == 0) { g_ix[pos] = i; g_clx[pos] = v; }
            else        { g_iy[pos] = i; g_cly[pos] = v; }
            if ((mask & lt) == 0) sBase[w][v] = myBase + __popc(mask);
            __syncwarp();
        }
    }
    __syncthreads();
    if (threadIdx.x == 0) {
        float lf = 0.f;
        int oXY = 0, oYX = 0, oXX = 0, oYY = 0;
        g_rowBase[0] = 0;
        for (int k = 0; k < KC; k++) {
            int cx = g_cntx[k], cy = g_cnty[k];
            float d = (float)cx / (float)NN - fill[k];
            lf += d * d;
            g_offXY[k] = oXY; g_offYX[k] = oYX; g_offXX[k] = oXX; g_offYY[k] = oYY;
            oXY += cx * cy; oYX += cy * cx; oXX += cx * cx; oYY += cy * cy;
            g_l2cx[k] = log2f((float)(cx > 0 ? cx : 1));
            g_l2cy[k] = log2f((float)(cy > 0 ? cy : 1));
            g_valid[k] = (cx > 0 && cy > 0) ? 1 : 0;
            g_rowBase[k + 1] = g_rowBase[k] + 2 * (cx + cy);
        }
        g_offXY[KC] = oXY; g_offYX[KC] = oYX; g_offXX[KC] = oXX; g_offYY[KC] = oYY;
        g_lossfil = lf / (float)KC;
        g_tOff[0] = 0;
        for (int f = 0; f < 4; f++)
            for (int k = 0; k < KC; k++) {
                int cx = g_cntx[k], cy = g_cnty[k];
                int nr = (f == 0 || f == 2) ? cx : cy;
                int nc = (f == 1 || f == 2) ? cx : cy;
                int idx = f * KC + k;
                g_tOff[idx + 1] = g_tOff[idx] + ((nr + 63) / 64) * ((nc + 63) / 64);
            }
    }
    __syncthreads();
    // row descriptors in cluster-contiguous order + potential init
    for (int row = threadIdx.x; row < NROWS; row += blockDim.x) {
        int kk = 0;
        while (row >= g_rowBase[kk + 1]) kk++;
        int off = row - g_rowBase[kk];
        int cx = g_cntx[kk], cy = g_cnty[kk];
        int n, potOff, outIdx; const float* C; float b2;
        if (off < cx) {                       // fab row
            int p = off;
            n = cy; C = g_Cxy + (size_t)g_offXY[kk] + (size_t)p * n;
            potOff = GAB_OFF + g_offy[kk]; b2 = -g_l2cy[kk];
            outIdx = FAB_OFF + g_offx[kk] + p;
        } else if (off < cx + cy) {           // gab row
            int p = off - cx;
            n = cx; C = g_Cyx + (size_t)g_offYX[kk] + (size_t)p * n;
            potOff = FAB_OFF + g_offx[kk]; b2 = -g_l2cx[kk];
            outIdx = GAB_OFF + g_offy[kk] + p;
        } else if (off < 2 * cx + cy) {       // faa row
            int p = off - cx - cy;
            n = cx; C = g_Cxx + (size_t)g_offXX[kk] + (size_t)p * n;
            potOff = FAA_OFF + g_offx[kk]; b2 = -g_l2cx[kk];
            outIdx = FAA_OFF + g_offx[kk] + p;
        } else {                              // gbb row
            int p = off - 2 * cx - cy;
            n = cy; C = g_Cyy + (size_t)g_offYY[kk] + (size_t)p * n;
            potOff = GBB_OFF + g_offy[kk]; b2 = -g_l2cy[kk];
            outIdx = GBB_OFF + g_offy[kk] + p;
        }
        g_rowC[row] = C; g_rowPotIn[row] = potOff; g_rowOut[row] = outIdx;
        g_rowN[row] = n; g_rowB2[row] = b2;
    }
    for (int i = threadIdx.x; i < POT_SZ; i += blockDim.x) g_pot[0][i] = 0.f;
}

// -------------------- 3) compact cost submatrices ---------------------------
__global__ __launch_bounds__(256) void k_cost(const float* __restrict__ x,
                                              const float* __restrict__ y) {
    __shared__ float sR[64][65];
    __shared__ float sCt[64][68];
    __shared__ float sHr[64], sHc[64];
    __shared__ int sOff[4 * KC + 1];
    int tid = threadIdx.x;
    if (tid < 4 * KC + 1) sOff[tid] = g_tOff[tid];
    __syncthreads();
    int bt = blockIdx.x;
    if (bt >= sOff[4 * KC]) return;
    int e = 0;
    while (bt >= sOff[e + 1]) e++;
    int f = e >> 3, k = e & 7;
    int ti = bt - sOff[e];
    int cx = g_cntx[k], cy = g_cnty[k], ox = g_offx[k], oy = g_offy[k];
    int nr, nc, obase;
    const int *rl, *cl; const float *rp, *cp, *rh, *chv; float* outp;
    if (f == 0)      { nr = cx; nc = cy; rl = g_ix + ox; cl = g_iy + oy; rp = x; cp = y; rh = g_hx; chv = g_hy; outp = g_Cxy; obase = g_offXY[k]; }
    else if (f == 1) { nr = cy; nc = cx; rl = g_iy + oy; cl = g_ix + ox; rp = y; cp = x; rh = g_hy; chv = g_hx; outp = g_Cyx; obase = g_offYX[k]; }
    else if (f == 2) { nr = cx; nc = cx; rl = g_ix + ox; cl = g_ix + ox; rp = x; cp = x; rh = g_hx; chv = g_hx; outp = g_Cxx; obase = g_offXX[k]; }
    else             { nr = cy; nc = cy; rl = g_iy + oy; cl = g_iy + oy; rp = y; cp = y; rh = g_hy; chv = g_hy; outp = g_Cyy; obase = g_offYY[k]; }
    int nct = (nc + 63) >> 6;
    int r0 = (ti / nct) * 64;
    int c0 = (ti % nct) * 64;

    for (int idx = tid; idx < 64 * DD; idx += 256) {
        int r = idx >> 6, d = idx & 63;
        int gi = rl[min(r0 + r, nr - 1)];
        sR[r][d] = rp[(size_t)gi * DD + d];
    }
    for (int idx = tid; idx < 64 * DD; idx += 256) {
        int c = idx >> 6, d = idx & 63;
        int gi = cl[min(c0 + c, nc - 1)];
        sCt[d][c] = cp[(size_t)gi * DD + d];
    }
    if (tid < 64)       sHr[tid]      = rh[rl[min(r0 + tid, nr - 1)]];
    else if (tid < 128) sHc[tid - 64] = chv[cl[min(c0 + tid - 64, nc - 1)]];
    __syncthreads();

    int rg = tid >> 4, cg = tid & 15;
    float acc[4][4];
#pragma unroll
    for (int i = 0; i < 4; i++)
#pragma unroll
        for (int j = 0; j < 4; j++) acc[i][j] = 0.f;

#pragma unroll 8
    for (int d = 0; d < DD; d++) {
        float4 cv = *reinterpret_cast<const float4*>(&sCt[d][cg * 4]);
        float r0v = sR[rg * 4 + 0][d];
        float r1v = sR[rg * 4 + 1][d];
        float r2v = sR[rg * 4 + 2][d];
        float r3v = sR[rg * 4 + 3][d];
        acc[0][0]=fmaf(r0v,cv.x,acc[0][0]); acc[0][1]=fmaf(r0v,cv.y,acc[0][1]);
        acc[0][2]=fmaf(r0v,cv.z,acc[0][2]); acc[0][3]=fmaf(r0v,cv.w,acc[0][3]);
        acc[1][0]=fmaf(r1v,cv.x,acc[1][0]); acc[1][1]=fmaf(r1v,cv.y,acc[1][1]);
        acc[1][2]=fmaf(r1v,cv.z,acc[1][2]); acc[1][3]=fmaf(r1v,cv.w,acc[1][3]);
        acc[2][0]=fmaf(r2v,cv.x,acc[2][0]); acc[2][1]=fmaf(r2v,cv.y,acc[2][1]);
        acc[2][2]=fmaf(r2v,cv.z,acc[2][2]); acc[2][3]=fmaf(r2v,cv.w,acc[2][3]);
        acc[3][0]=fmaf(r3v,cv.x,acc[3][0]); acc[3][1]=fmaf(r3v,cv.y,acc[3][1]);
        acc[3][2]=fmaf(r3v,cv.z,acc[3][2]); acc[3][3]=fmaf(r3v,cv.w,acc[3][3]);
    }

#pragma unroll
    for (int i = 0; i < 4; i++) {
        int rr = r0 + rg * 4 + i;
        if (rr < nr) {
            float hr = sHr[rg * 4 + i];
            size_t rowb = (size_t)obase + (size_t)rr * nc;
#pragma unroll
            for (int j = 0; j < 4; j++) {
                int cc = c0 + cg * 4 + j;
                if (cc < nc) outp[rowb + cc] = fmaxf(hr + sHc[cg * 4 + j] - acc[i][j], 0.f);
            }
        }
    }
}

// -------------------- 4) CGA-synchronized Sinkhorn rounds -------------------
// one-pass online logsumexp over a row of any length; 256-col register tiles.
__device__ __forceinline__ void sink_row(int row, const float* __restrict__ potIn,
                                         float* __restrict__ potOut,
                                         float eps, float s1, int finalMode, int lane) {
    int n = g_rowN[row];
    int outIdx = g_rowOut[row];
    if (n == 0) {
        if (lane == 0) potOut[outIdx] = 0.f;
        return;
    }
    const float* __restrict__ Crow = g_rowC[row];
    const float* __restrict__ pot = potIn + g_rowPotIn[row];
    float b2 = g_rowB2[row];

    float m = SENT, S = 0.f;
    for (int base = 0; base < n; base += 256) {
        int lim = n - base;                      // >= 1
        float tv[8];
#pragma unroll
        for (int q = 0; q < 8; q++) {
            float v = SENT;
            if (q * 32 < lim) {                  // warp-uniform
                int idx = q * 32 + lane;
                int c = base + min(idx, lim - 1);
                v = fmaf(pot[c] - Crow[c], s1, b2);
                if (idx >= lim) v = SENT;
            }
            tv[q] = v;
        }
        float mt = tv[0];
#pragma unroll
        for (int q = 1; q < 8; q++) mt = fmaxf(mt, tv[q]);
        float c2 = fmaxf(m, mt);
        float Sn = S * ex2_fast(m - c2);
#pragma unroll
        for (int q = 0; q < 8; q++) Sn += ex2_fast(tv[q] - c2);   // masked: ex2(SENT-c2)=0
        m = c2; S = Sn;
    }
#pragma unroll
    for (int o = 16; o; o >>= 1) {
        float mo = __shfl_xor_sync(0xffffffffu, m, o);
        float So = __shfl_xor_sync(0xffffffffu, S, o);
        float c2 = fmaxf(m, mo);
        S = S * ex2_fast(m - c2) + So * ex2_fast(mo - c2);
        m = c2;
    }
    if (lane == 0) {
        float lse = (m + log2f(S)) * LN2_F;
        float outv = -eps * lse;
        potOut[outIdx] = finalMode ? outv : 0.5f * (potIn[outIdx] + outv);
    }
}

__global__ __launch_bounds__(1024, 1) __cluster_dims__(CGA_SZ, 1, 1)
void k_rounds() {
    __shared__ float seps[24], sinv[24];
    __shared__ int sns;
    int tid = threadIdx.x, lane = tid & 31;
    if (tid == 0) {
        double e = 16.0; int c = 0;
        while (e > 0.0025) { seps[c] = (float)e; sinv[c] = (float)(1.0 / (double)(float)e); c++; e *= 0.64; }
        seps[c] = 0.0025f; sinv[c] = (float)(1.0 / (double)0.0025f); c++;
        sns = c;
    }
    __syncthreads();
    int ns = sns;
    int k = blockIdx.x >> 3;                    // CGA id == kmeans cluster id
    int rlo = g_rowBase[k], rhi = g_rowBase[k + 1];
    int lw = ((blockIdx.x & 7) << 5) + (tid >> 5);   // warp id within CGA: 0..255

    for (int s = 0; s <= ns; s++) {
        int fin = (s == ns);
        int ei = fin ? ns - 1 : s;
        float eps = seps[ei];
        float s1 = sinv[ei] * LOG2E_F;
        const float* potIn = g_pot[s & 1];
        float* potOut = g_pot[(s + 1) & 1];
        for (int row = rlo + lw; row < rhi; row += CGA_SZ * 32)
            sink_row(row, potIn, potOut, eps, s1, fin, lane);
        // per-cluster barrier with release/acquire + L1D invalidate:
        // __threadfence() (gpu scope) emits CCTL.IVALL, so post-wait loads
        // can't hit stale L1 lines of the ping-pong potential buffers.
        __threadfence();
        asm volatile("barrier.cluster.arrive.aligned;" ::: "memory");
        asm volatile("barrier.cluster.wait.aligned;" ::: "memory");
        __threadfence();
    }
}

// -------------------- 5) final divergence reduction -------------------------
__global__ void k_reduce(int buf, float* __restrict__ out) {
    __shared__ float sred[256];
    const float* pf = g_pot[buf];
    float acc = 0.f;
    for (int p = threadIdx.x; p < NN; p += 256) {
        int k = g_clx[p];
        if (g_valid[k]) acc += (pf[FAB_OFF + p] - pf[FAA_OFF + p]) / (float)g_cntx[k];
    }
    for (int p = threadIdx.x; p < MM; p += 256) {
        int k = g_cly[p];
        if (g_valid[k]) acc += (pf[GAB_OFF + p] - pf[GBB_OFF + p]) / (float)g_cnty[k];
    }
    sred[threadIdx.x] = acc;
    __syncthreads();
    for (int s = 128; s; s >>= 1) {
        if (threadIdx.x < s) sred[threadIdx.x] += sred[threadIdx.x + s];
        __syncthreads();
    }
    if (threadIdx.x == 0) out[0] = sred[0] + g_lossfil;
}

// -------------------- host launch -------------------------------------------
extern "C" void kernel_launch(void* const* d_in, const int* in_sizes, int n_in,
                              void* d_out, int out_size) {
    const float* x    = (const float*)d_in[0];
    const float* cc   = (const float*)d_in[1];
    const float* fill = (const float*)d_in[2];
    const float* y    = (const float*)d_in[3];
    const int*   pred = (const int*)d_in[4];
    float* out = (float*)d_out;

    k_prep<<<(NN + MM + 255) / 256, 256>>>(x, cc, y);
    k_lists<<<1, 256>>>(pred, fill);
    k_cost<<<COST_GRID, 256>>>(x, y);
    k_rounds<<<ROUND_GRID, 1024>>>();

    // same schedule as device: ns entries incl. eps_min; final buffer = (ns+1)&1
    int ns = 0; double e = 16.0;
    while (e > 0.0025) { ns++; e *= 0.64; }
    ns++;
    k_reduce<<<1, 256>>>((ns + 1) & 1, out);
}

// round 9
// speedup vs baseline: 3.1536x; 3.1536x over previous
#include <cuda_runtime.h>
#include <math.h>

#define NN 2048
#define MM 2048
#define KC 8
#define DD 64

#define FAB_OFF 0
#define GAB_OFF NN
#define FAA_OFF (NN + MM)
#define GBB_OFF (2 * NN + MM)
#define POT_SZ  (2 * (NN + MM))
#define NROWS   (2 * (NN + MM))

#define LOG2E_F 1.4426950408889634f
#define LN2_F   0.6931471805599453f
#define SENT    -3.4e38f

#define GRIDB 148
#define COST_GRID 4416

// -------------------- static device scratch ---------------------------------
__device__ int   g_predx[NN];
__device__ int   g_ix[NN], g_iy[MM];
__device__ int   g_clx[NN], g_cly[MM];
__device__ int   g_cntx[KC], g_cnty[KC];
__device__ int   g_offx[KC + 1], g_offy[KC + 1];
__device__ int   g_offXY[KC + 1], g_offYX[KC + 1], g_offXX[KC + 1], g_offYY[KC + 1];
__device__ float g_l2cx[KC], g_l2cy[KC];
__device__ int   g_valid[KC];
__device__ float g_lossfil;
__device__ int   g_tOff[4 * KC + 1];
__device__ int   g_rowBase[KC + 1];
__device__ float g_hx[NN], g_hy[MM];
__device__ unsigned g_barCnt;
__device__ unsigned g_exitCnt;
// row descriptors (computed once, read every round)
__device__ const float* g_rowC[NROWS];
__device__ int   g_rowPotIn[NROWS];
__device__ int   g_rowOut[NROWS];
__device__ int   g_rowN[NROWS];
__device__ float g_rowB2[NROWS];
// cost matrices
__device__ float g_Cxy[(size_t)NN * MM];
__device__ float g_Cyx[(size_t)NN * MM];
__device__ float g_Cxx[(size_t)NN * NN];
__device__ float g_Cyy[(size_t)MM * MM];
__device__ float g_pot[2][POT_SZ];

__device__ __forceinline__ float ex2_fast(float x) {
    float r;
    asm("ex2.approx.ftz.f32 %0, %1;" : "=f"(r) : "f"(x));
    return r;
}
// release/acquire barrier ops (no CCTL.IVALL -> L1 keeps cost matrices hot)
__device__ __forceinline__ void red_release_add1(unsigned* p) {
    asm volatile("red.release.gpu.add.u32 [%0], 1;" :: "l"(p) : "memory");
}
__device__ __forceinline__ unsigned ld_acquire_u32(unsigned* p) {
    unsigned v;
    asm volatile("ld.acquire.gpu.u32 %0, [%1];" : "=r"(v) : "l"(p) : "memory");
    return v;
}

// -------------------- 1) fused assign + norms -------------------------------
__global__ void k_prep(const float* __restrict__ x, const float* __restrict__ cc,
                       const float* __restrict__ y) {
    __shared__ float scc[KC * DD];
    for (int idx = threadIdx.x; idx < KC * DD; idx += blockDim.x) scc[idx] = cc[idx];
    __syncthreads();
    int t = blockIdx.x * blockDim.x + threadIdx.x;
    if (t < NN) {
        float xr[DD];
        float nrm = 0.f;
        const float4* xv = reinterpret_cast<const float4*>(x + (size_t)t * DD);
#pragma unroll
        for (int q = 0; q < DD / 4; q++) {
            float4 v = xv[q];
            xr[q*4+0]=v.x; xr[q*4+1]=v.y; xr[q*4+2]=v.z; xr[q*4+3]=v.w;
            nrm += v.x*v.x + v.y*v.y + v.z*v.z + v.w*v.w;
        }
        g_hx[t] = 0.5f * nrm;
        float best = 3.4e38f; int bk = 0;
#pragma unroll
        for (int k = 0; k < KC; k++) {
            float s = 0.f;
#pragma unroll 16
            for (int d = 0; d < DD; d++) {
                float u = xr[d] - scc[k * DD + d];
                s = fmaf(u, u, s);
            }
            if (s < best) { best = s; bk = k; }
        }
        g_predx[t] = bk;
    } else if (t < NN + MM) {
        int j = t - NN;
        const float4* v = reinterpret_cast<const float4*>(y + (size_t)j * DD);
        float s = 0.f;
#pragma unroll
        for (int q = 0; q < DD / 4; q++) { float4 a = v[q]; s += a.x*a.x + a.y*a.y + a.z*a.z + a.w*a.w; }
        g_hy[j] = 0.5f * s;
    }
}

// -------------------- 2) lists + offsets + row descriptors ------------------
__global__ void k_lists(const int* __restrict__ predy32, const float* __restrict__ fill) {
    __shared__ int sBase[2][KC];
    __shared__ int sCnt[2][KC];
    __shared__ int sOr;
    int w = threadIdx.x >> 5, lane = threadIdx.x & 31;

    if (threadIdx.x == 0) sOr = 0;
    __syncthreads();
    int orv = 0;
    for (int i = threadIdx.x; i < MM / 2; i += blockDim.x) orv |= predy32[2 * i + 1];
    atomicOr(&sOr, orv);
    __syncthreads();
    const int stride = (sOr == 0) ? 2 : 1;   // int64 (odd words 0) vs int32

    if (w < 2) {
        int nElem = (w == 0) ? NN : MM;
        int cnt[KC];
#pragma unroll
        for (int k = 0; k < KC; k++) cnt[k] = 0;
        for (int ch = 0; ch < nElem / 32; ch++) {
            int i = ch * 32 + lane;
            int v = (w == 0) ? g_predx[i] : (predy32[i * stride] & 7);
#pragma unroll
            for (int k = 0; k < KC; k++) cnt[k] += (v == k);
        }
#pragma unroll
        for (int k = 0; k < KC; k++) {
            int s = cnt[k];
            for (int o = 16; o; o >>= 1) s += __shfl_down_sync(0xffffffffu, s, o);
            if (lane == 0) sCnt[w][k] = s;
        }
        __syncwarp();
        if (lane == 0) {
            int off = 0;
            for (int k = 0; k < KC; k++) {
                int c = sCnt[w][k];
                sBase[w][k] = off;
                if (w == 0) { g_cntx[k] = c; g_offx[k] = off; }
                else        { g_cnty[k] = c; g_offy[k] = off; }
                off += c;
            }
            if (w == 0) g_offx[KC] = off; else g_offy[KC] = off;
        }
        __syncwarp();
        for (int ch = 0; ch < nElem / 32; ch++) {
            int i = ch * 32 + lane;
            int v = (w == 0) ? g_predx[i] : (predy32[i * stride] & 7);
            unsigned mask = __match_any_sync(0xffffffffu, v);
            unsigned lt = (1u << lane) - 1u;
            int rank = __popc(mask & lt);
            int myBase = sBase[w][v];
            __syncwarp();
            int pos = myBase + rank;
            if (w == 0) { g_ix[pos] = i; g_clx[pos] = v; }
            else        { g_iy[pos] = i; g_cly[pos] = v; }
            if ((mask & lt) == 0) sBase[w][v] = myBase + __popc(mask);
            __syncwarp();
        }
    }
    __syncthreads();
    if (threadIdx.x == 0) {
        float lf = 0.f;
        int oXY = 0, oYX = 0, oXX = 0, oYY = 0;
        g_rowBase[0] = 0;
        for (int k = 0; k < KC; k++) {
            int cx = g_cntx[k], cy = g_cnty[k];
            float d = (float)cx / (float)NN - fill[k];
            lf += d * d;
            g_offXY[k] = oXY; g_offYX[k] = oYX; g_offXX[k] = oXX; g_offYY[k] = oYY;
            oXY += cx * cy; oYX += cy * cx; oXX += cx * cx; oYY += cy * cy;
            g_l2cx[k] = log2f((float)(cx > 0 ? cx : 1));
            g_l2cy[k] = log2f((float)(cy > 0 ? cy : 1));
            g_valid[k] = (cx > 0 && cy > 0) ? 1 : 0;
            g_rowBase[k + 1] = g_rowBase[k] + 2 * (cx + cy);
        }
        g_offXY[KC] = oXY; g_offYX[KC] = oYX; g_offXX[KC] = oXX; g_offYY[KC] = oYY;
        g_lossfil = lf / (float)KC;
        g_tOff[0] = 0;
        for (int f = 0; f < 4; f++)
            for (int k = 0; k < KC; k++) {
                int cx = g_cntx[k], cy = g_cnty[k];
                int nr = (f == 0 || f == 2) ? cx : cy;
                int nc = (f == 1 || f == 2) ? cx : cy;
                int idx = f * KC + k;
                g_tOff[idx + 1] = g_tOff[idx] + ((nr + 63) / 64) * ((nc + 63) / 64);
            }
    }
    __syncthreads();
    // row descriptors in cluster-contiguous order + potential init
    for (int row = threadIdx.x; row < NROWS; row += blockDim.x) {
        int kk = 0;
        while (row >= g_rowBase[kk + 1]) kk++;
        int off = row - g_rowBase[kk];
        int cx = g_cntx[kk], cy = g_cnty[kk];
        int n, potOff, outIdx; const float* C; float b2;
        if (off < cx) {                       // fab row
            int p = off;
            n = cy; C = g_Cxy + (size_t)g_offXY[kk] + (size_t)p * n;
            potOff = GAB_OFF + g_offy[kk]; b2 = -g_l2cy[kk];
            outIdx = FAB_OFF + g_offx[kk] + p;
        } else if (off < cx + cy) {           // gab row
            int p = off - cx;
            n = cx; C = g_Cyx + (size_t)g_offYX[kk] + (size_t)p * n;
            potOff = FAB_OFF + g_offx[kk]; b2 = -g_l2cx[kk];
            outIdx = GAB_OFF + g_offy[kk] + p;
        } else if (off < 2 * cx + cy) {       // faa row
            int p = off - cx - cy;
            n = cx; C = g_Cxx + (size_t)g_offXX[kk] + (size_t)p * n;
            potOff = FAA_OFF + g_offx[kk]; b2 = -g_l2cx[kk];
            outIdx = FAA_OFF + g_offx[kk] + p;
        } else {                              // gbb row
            int p = off - 2 * cx - cy;
            n = cy; C = g_Cyy + (size_t)g_offYY[kk] + (size_t)p * n;
            potOff = GBB_OFF + g_offy[kk]; b2 = -g_l2cy[kk];
            outIdx = GBB_OFF + g_offy[kk] + p;
        }
        g_rowC[row] = C; g_rowPotIn[row] = potOff; g_rowOut[row] = outIdx;
        g_rowN[row] = n; g_rowB2[row] = b2;
    }
    for (int i = threadIdx.x; i < POT_SZ; i += blockDim.x) g_pot[0][i] = 0.f;
}

// -------------------- 3) compact cost submatrices ---------------------------
__global__ __launch_bounds__(256) void k_cost(const float* __restrict__ x,
                                              const float* __restrict__ y) {
    __shared__ float sR[64][65];
    __shared__ float sCt[64][68];
    __shared__ float sHr[64], sHc[64];
    __shared__ int sOff[4 * KC + 1];
    int tid = threadIdx.x;
    if (tid < 4 * KC + 1) sOff[tid] = g_tOff[tid];
    __syncthreads();
    int bt = blockIdx.x;
    if (bt >= sOff[4 * KC]) return;
    int e = 0;
    while (bt >= sOff[e + 1]) e++;
    int f = e >> 3, k = e & 7;
    int ti = bt - sOff[e];
    int cx = g_cntx[k], cy = g_cnty[k], ox = g_offx[k], oy = g_offy[k];
    int nr, nc, obase;
    const int *rl, *cl; const float *rp, *cp, *rh, *chv; float* outp;
    if (f == 0)      { nr = cx; nc = cy; rl = g_ix + ox; cl = g_iy + oy; rp = x; cp = y; rh = g_hx; chv = g_hy; outp = g_Cxy; obase = g_offXY[k]; }
    else if (f == 1) { nr = cy; nc = cx; rl = g_iy + oy; cl = g_ix + ox; rp = y; cp = x; rh = g_hy; chv = g_hx; outp = g_Cyx; obase = g_offYX[k]; }
    else if (f == 2) { nr = cx; nc = cx; rl = g_ix + ox; cl = g_ix + ox; rp = x; cp = x; rh = g_hx; chv = g_hx; outp = g_Cxx; obase = g_offXX[k]; }
    else             { nr = cy; nc = cy; rl = g_iy + oy; cl = g_iy + oy; rp = y; cp = y; rh = g_hy; chv = g_hy; outp = g_Cyy; obase = g_offYY[k]; }
    int nct = (nc + 63) >> 6;
    int r0 = (ti / nct) * 64;
    int c0 = (ti % nct) * 64;

    for (int idx = tid; idx < 64 * DD; idx += 256) {
        int r = idx >> 6, d = idx & 63;
        int gi = rl[min(r0 + r, nr - 1)];
        sR[r][d] = rp[(size_t)gi * DD + d];
    }
    for (int idx = tid; idx < 64 * DD; idx += 256) {
        int c = idx >> 6, d = idx & 63;
        int gi = cl[min(c0 + c, nc - 1)];
        sCt[d][c] = cp[(size_t)gi * DD + d];
    }
    if (tid < 64)       sHr[tid]      = rh[rl[min(r0 + tid, nr - 1)]];
    else if (tid < 128) sHc[tid - 64] = chv[cl[min(c0 + tid - 64, nc - 1)]];
    __syncthreads();

    int rg = tid >> 4, cg = tid & 15;
    float acc[4][4];
#pragma unroll
    for (int i = 0; i < 4; i++)
#pragma unroll
        for (int j = 0; j < 4; j++) acc[i][j] = 0.f;

#pragma unroll 8
    for (int d = 0; d < DD; d++) {
        float4 cv = *reinterpret_cast<const float4*>(&sCt[d][cg * 4]);
        float r0v = sR[rg * 4 + 0][d];
        float r1v = sR[rg * 4 + 1][d];
        float r2v = sR[rg * 4 + 2][d];
        float r3v = sR[rg * 4 + 3][d];
        acc[0][0]=fmaf(r0v,cv.x,acc[0][0]); acc[0][1]=fmaf(r0v,cv.y,acc[0][1]);
        acc[0][2]=fmaf(r0v,cv.z,acc[0][2]); acc[0][3]=fmaf(r0v,cv.w,acc[0][3]);
        acc[1][0]=fmaf(r1v,cv.x,acc[1][0]); acc[1][1]=fmaf(r1v,cv.y,acc[1][1]);
        acc[1][2]=fmaf(r1v,cv.z,acc[1][2]); acc[1][3]=fmaf(r1v,cv.w,acc[1][3]);
        acc[2][0]=fmaf(r2v,cv.x,acc[2][0]); acc[2][1]=fmaf(r2v,cv.y,acc[2][1]);
        acc[2][2]=fmaf(r2v,cv.z,acc[2][2]); acc[2][3]=fmaf(r2v,cv.w,acc[2][3]);
        acc[3][0]=fmaf(r3v,cv.x,acc[3][0]); acc[3][1]=fmaf(r3v,cv.y,acc[3][1]);
        acc[3][2]=fmaf(r3v,cv.z,acc[3][2]); acc[3][3]=fmaf(r3v,cv.w,acc[3][3]);
    }

#pragma unroll
    for (int i = 0; i < 4; i++) {
        int rr = r0 + rg * 4 + i;
        if (rr < nr) {
            float hr = sHr[rg * 4 + i];
            size_t rowb = (size_t)obase + (size_t)rr * nc;
#pragma unroll
            for (int j = 0; j < 4; j++) {
                int cc = c0 + cg * 4 + j;
                if (cc < nc) outp[rowb + cc] = fmaxf(hr + sHc[cg * 4 + j] - acc[i][j], 0.f);
            }
        }
    }
}

// -------------------- 4) persistent Sinkhorn rounds (L1-preserving) ---------
// pot: smem snapshot (loaded via __ldcg), writes via __stcg; C: L1-cached, immutable.
__device__ __forceinline__ void sink_row(int row, const float* __restrict__ sPot,
                                         float* __restrict__ potOut,
                                         float eps, float s1, int finalMode, int lane) {
    int n = g_rowN[row];
    int outIdx = g_rowOut[row];
    if (n == 0) {
        if (lane == 0) __stcg(&potOut[outIdx], 0.f);
        return;
    }
    const float* __restrict__ Crow = g_rowC[row];
    const float* __restrict__ pot = sPot + g_rowPotIn[row];
    float b2 = g_rowB2[row];

    float m = SENT, S = 0.f;
    for (int base = 0; base < n; base += 256) {
        int lim = n - base;                      // >= 1
        float tv[8];
#pragma unroll
        for (int q = 0; q < 8; q++) {
            float v = SENT;
            if (q * 32 < lim) {                  // warp-uniform
                int idx = q * 32 + lane;
                int c = base + min(idx, lim - 1);
                v = fmaf(pot[c] - Crow[c], s1, b2);
                if (idx >= lim) v = SENT;
            }
            tv[q] = v;
        }
        float mt = tv[0];
#pragma unroll
        for (int q = 1; q < 8; q++) mt = fmaxf(mt, tv[q]);
        float c2 = fmaxf(m, mt);
        float Sn = S * ex2_fast(m - c2);
#pragma unroll
        for (int q = 0; q < 8; q++) Sn += ex2_fast(tv[q] - c2);   // masked: ex2(SENT-c2)=0
        m = c2; S = Sn;
    }
#pragma unroll
    for (int o = 16; o; o >>= 1) {
        float mo = __shfl_xor_sync(0xffffffffu, m, o);
        float So = __shfl_xor_sync(0xffffffffu, S, o);
        float c2 = fmaxf(m, mo);
        S = S * ex2_fast(m - c2) + So * ex2_fast(mo - c2);
        m = c2;
    }
    if (lane == 0) {
        float lse = (m + log2f(S)) * LN2_F;
        float outv = -eps * lse;
        __stcg(&potOut[outIdx], finalMode ? outv : 0.5f * (sPot[outIdx] + outv));
    }
}

__global__ __launch_bounds__(1024, 1) void k_rounds(float* __restrict__ out) {
    __shared__ float sPot[POT_SZ];              // 32KB snapshot of potIn
    __shared__ float seps[24], sinv[24];
    __shared__ int sns;
    __shared__ float sred[1024];
    int tid = threadIdx.x, lane = tid & 31;
    int gwarp = blockIdx.x * 32 + (tid >> 5);
    int nwarps = gridDim.x * 32;
    if (tid == 0) {
        double e = 16.0; int c = 0;
        while (e > 0.0025) { seps[c] = (float)e; sinv[c] = (float)(1.0 / (double)(float)e); c++; e *= 0.64; }
        seps[c] = 0.0025f; sinv[c] = (float)(1.0 / (double)0.0025f); c++;
        sns = c;
    }
    __syncthreads();
    int ns = sns;
    for (int s = 0; s <= ns; s++) {
        int fin = (s == ns);
        int ei = fin ? ns - 1 : s;
        float eps = seps[ei];
        float s1 = sinv[ei] * LOG2E_F;
        const float* potIn = g_pot[s & 1];
        float* potOut = g_pot[(s + 1) & 1];
        // snapshot potentials (L2-coherent reads; pot never lives in L1)
        for (int i = tid; i < POT_SZ; i += 1024) sPot[i] = __ldcg(potIn + i);
        __syncthreads();
        for (int row = gwarp; row < NROWS; row += nwarps)
            sink_row(row, sPot, potOut, eps, s1, fin, lane);
        // grid barrier: release/acquire by thread 0 only — no L1 flush
        __syncthreads();
        if (tid == 0) {
            red_release_add1(&g_barCnt);
            unsigned target = (unsigned)(s + 1) * gridDim.x;
            while (ld_acquire_u32(&g_barCnt) < target) { }
        }
        __syncthreads();
    }
    if (blockIdx.x != 0) {
        if (tid == 0) red_release_add1(&g_exitCnt);
        return;
    }
    // block 0: final divergence reduction (pot via __ldcg: L2-coherent)
    const float* pf = g_pot[(ns + 1) & 1];
    float acc = 0.f;
    for (int p = tid; p < NN; p += 1024) {
        int k = g_clx[p];
        if (g_valid[k]) acc += (__ldcg(&pf[FAB_OFF + p]) - __ldcg(&pf[FAA_OFF + p])) / (float)g_cntx[k];
    }
    for (int p = tid; p < MM; p += 1024) {
        int k = g_cly[p];
        if (g_valid[k]) acc += (__ldcg(&pf[GAB_OFF + p]) - __ldcg(&pf[GBB_OFF + p])) / (float)g_cnty[k];
    }
    sred[tid] = acc;
    __syncthreads();
    for (int s = 512; s; s >>= 1) {
        if (tid < s) sred[tid] += sred[tid + s];
        __syncthreads();
    }
    if (tid == 0) {
        out[0] = sred[0] + g_lossfil;
        // safe counter reset: wait until all other blocks are past their last poll
        while (ld_acquire_u32(&g_exitCnt) < (unsigned)(gridDim.x - 1)) { }
        *((volatile unsigned*)&g_barCnt) = 0;
        *((volatile unsigned*)&g_exitCnt) = 0;
    }
}

// -------------------- host launch -------------------------------------------
extern "C" void kernel_launch(void* const* d_in, const int* in_sizes, int n_in,
                              void* d_out, int out_size) {
    const float* x    = (const float*)d_in[0];
    const float* cc   = (const float*)d_in[1];
    const float* fill = (const float*)d_in[2];
    const float* y    = (const float*)d_in[3];
    const int*   pred = (const int*)d_in[4];
    float* out = (float*)d_out;

    k_prep<<<(NN + MM + 255) / 256, 256>>>(x, cc, y);
    k_lists<<<1, 256>>>(pred, fill);
    k_cost<<<COST_GRID, 256>>>(x, y);
    k_rounds<<<GRIDB, 1024>>>(out);
}